// round 16
// baseline (speedup 1.0000x reference)
#include <cuda_runtime.h>
#include <cstdint>

#define TOK    16384
#define DIM    2048
#define NE     16
#define BT     128
#define NTHR   512
#define NCHUNK 32

// smem: A stages [0, 65536): half h at h*32768, stage s at +s*16384 (hi 8K | lo 8K)
//       W blob [65536, 196608)
#define WB 65536u
#define SMEM_BYTES (65536 + 131072 + 1024)   // 197632

__device__ __forceinline__ uint32_t smem_u32(const void* p) {
    uint32_t a;
    asm("{ .reg .u64 t; cvta.to.shared.u64 t, %1; cvt.u32.u64 %0, t; }" : "=r"(a) : "l"(p));
    return a;
}

#define STS32U(addr, v) asm volatile("st.shared.b32 [%0], %1;" :: "r"(addr), "r"(v) : "memory")
#define STS64U(addr, a, b) \
    asm volatile("st.shared.v2.b32 [%0], {%1, %2};" :: "r"(addr), "r"(a), "r"(b) : "memory")
#define STS64F(addr, a, b) \
    asm volatile("st.shared.v2.f32 [%0], {%1, %2};" :: "r"(addr), "f"(a), "f"(b) : "memory")
#define LDS32F(v, addr) asm volatile("ld.shared.f32 %0, [%1];" : "=f"(v) : "r"(addr))
#define LDS32U(v, addr) asm volatile("ld.shared.b32 %0, [%1];" : "=r"(v) : "r"(addr))

#define BAR_HALF(id) asm volatile("bar.sync %0, %1;" :: "r"(id), "r"(256) : "memory")

#define LDMX4(r0, r1, r2, r3, addr) \
    asm volatile("ldmatrix.sync.aligned.m8n8.x4.shared.b16 {%0,%1,%2,%3}, [%4];" \
        : "=r"(r0), "=r"(r1), "=r"(r2), "=r"(r3) : "r"(addr))

#define MMA_BF16(d, a0, a1, a2, a3, b0, b1)                                \
    asm volatile("mma.sync.aligned.m16n8k16.row.col.f32.bf16.bf16.f32 "    \
        "{%0,%1,%2,%3},{%4,%5,%6,%7},{%8,%9},{%0,%1,%2,%3};"               \
        : "+f"(d[0]), "+f"(d[1]), "+f"(d[2]), "+f"(d[3])                   \
        : "r"(a0), "r"(a1), "r"(a2), "r"(a3), "r"(b0), "r"(b1))

// f32 pair -> packed bf16x2 hi (truncation; low half = f0) + bf16x2 lo (rounded residual)
__device__ __forceinline__ void cvt_pair(float f0, float f1, uint32_t& hi, uint32_t& lo) {
    uint32_t u0 = __float_as_uint(f0) & 0xffff0000u;
    uint32_t u1 = __float_as_uint(f1) & 0xffff0000u;
    asm("prmt.b32 %0, %1, %2, 0x7632;" : "=r"(hi) : "r"(u0), "r"(u1));
    float l0 = f0 - __uint_as_float(u0);
    float l1 = f1 - __uint_as_float(u1);
    asm("cvt.rn.bf16x2.f32 %0, %1, %2;" : "=r"(lo) : "f"(l1), "f"(l0));
}

__global__ void __launch_bounds__(NTHR, 1)
gating_moe_kernel(const float* __restrict__ x,
                  const float* __restrict__ noise,
                  const float* __restrict__ W,
                  const float* __restrict__ b,
                  float* __restrict__ out)
{
    extern __shared__ float sm[];
    const uint32_t sb = smem_u32(sm);
    const int tid  = threadIdx.x;
    const int l    = tid & 31;
    const int w    = tid >> 5;
    const int h    = w >> 3;         // half id (0: tokens 0-63, 1: 64-127)
    const int wl   = w & 7;          // warp within half
    const int tgh  = wl & 3;         // token group of 16 within half
    const int kh   = wl >> 2;        // k-half (kg 0-1 / 2-3)
    const int tok0 = blockIdx.x * BT;

    // ---- one-time W split blob (identical to R15, proven) ----
    #pragma unroll
    for (int k = 0; k < 32; k++) {
        int idx = tid + NTHR * k;
        int e   = idx >> 10;
        int pd  = idx & 1023;
        float2 wv = *(const float2*)(W + (size_t)e * DIM + 2 * pd);
        uint32_t hh, lo;
        cvt_pair(wv.x, wv.y, hh, lo);
        int kgg = pd >> 3;
        int p   = pd & 7;
        uint32_t base = WB + (uint32_t)(kgg * 1024 + (e >> 3) * 512);
        uint32_t off  = (uint32_t)((p >> 2) * 128 + (e & 7) * 16 + (p & 3) * 4);
        STS32U(sb + base + off, hh);
        STS32U(sb + base + off + 256u, lo);
    }

    // ---- producer mapping (per half: 256 threads fill 64 tokens x 64 dims) ----
    const int pt  = tid & 255;           // thread within half
    const int r0q = pt >> 4;             // local row base (u-th load: +16u)
    const int sl  = pt & 15;             // 4-float slice
    const float* xg = x + (size_t)(tok0 + h * 64 + r0q) * DIM + sl * 4;
    const uint32_t hreg = sb + (uint32_t)h * 32768u;
    uint32_t stsH[4];
    #pragma unroll
    for (int u = 0; u < 4; u++) {
        uint32_t o = (uint32_t)(((r0q + 16 * u) * 128) + sl * 8);
        stsH[u] = o ^ ((o >> 3) & 0x70u);
    }

    // ---- consumer geometry ----
    const uint32_t rowterm = (uint32_t)((tgh * 16 + (l & 15)) * 128 + ((l >> 4) << 4));
    const uint32_t lanB    = (uint32_t)((l >> 2) * 16 + (l & 3) * 4);

    float d0[4] = {0.f, 0.f, 0.f, 0.f};   // experts 0-7
    float d1[4] = {0.f, 0.f, 0.f, 0.f};   // experts 8-15
    float4 xv[2][4];                       // LDG prefetch distance 2

    // prologue: LDG chunks 0,1; STS chunk 0 into stage 0
    #pragma unroll
    for (int u = 0; u < 4; u++) {
        xv[0][u] = *(const float4*)(xg + u * 16 * DIM);
        xv[1][u] = *(const float4*)(xg + 64 + u * 16 * DIM);
    }
    #pragma unroll
    for (int u = 0; u < 4; u++) {
        uint32_t h0, h1, l0, l1;
        cvt_pair(xv[0][u].x, xv[0][u].y, h0, l0);
        cvt_pair(xv[0][u].z, xv[0][u].w, h1, l1);
        STS64U(hreg + stsH[u], h0, h1);
        STS64U(hreg + 8192u + stsH[u], l0, l1);
    }
    __syncthreads();    // W blob + both halves' stage 0 visible

    for (int c = 0; c < NCHUNK; c++) {
        // LDG chunk c+2 into the buffer freed by chunk c
        if (c + 2 < NCHUNK) {
            #pragma unroll
            for (int u = 0; u < 4; u++)
                xv[c & 1][u] = *(const float4*)(xg + (c + 2) * 64 + u * 16 * DIM);
        }

        // ---- consume stage c&1 (this half) ----
        const uint32_t ab = hreg + (uint32_t)(c & 1) * 16384u;
        #pragma unroll
        for (int kgl = 0; kgl < 2; kgl++) {
            const int kg = kh * 2 + kgl;
            uint32_t lg = rowterm + (uint32_t)(kg * 32);
            uint32_t sw = lg ^ ((lg >> 3) & 0x70u);
            uint32_t ah0, ah1, ah2, ah3, al0, al1, al2, al3;
            LDMX4(ah0, ah1, ah2, ah3, ab + sw);
            LDMX4(al0, al1, al2, al3, ab + 8192u + sw);

            const uint32_t kb = sb + WB + (uint32_t)((c * 4 + kg) * 1024) + lanB;
            uint32_t b0h0, b0h1, b0l0, b0l1, b1h0, b1h1, b1l0, b1l1;
            LDS32U(b0h0, kb);           LDS32U(b0h1, kb + 128u);
            LDS32U(b0l0, kb + 256u);    LDS32U(b0l1, kb + 384u);
            LDS32U(b1h0, kb + 512u);    LDS32U(b1h1, kb + 640u);
            LDS32U(b1l0, kb + 768u);    LDS32U(b1l1, kb + 896u);

            MMA_BF16(d0, ah0, ah1, ah2, ah3, b0h0, b0h1);
            MMA_BF16(d0, ah0, ah1, ah2, ah3, b0l0, b0l1);
            MMA_BF16(d0, al0, al1, al2, al3, b0h0, b0h1);
            MMA_BF16(d1, ah0, ah1, ah2, ah3, b1h0, b1h1);
            MMA_BF16(d1, ah0, ah1, ah2, ah3, b1l0, b1l1);
            MMA_BF16(d1, al0, al1, al2, al3, b1h0, b1h1);
        }

        // ---- produce chunk c+1 into the other stage, then half-barrier ----
        if (c + 1 < NCHUNK) {
            const uint32_t hb = hreg + (uint32_t)((c + 1) & 1) * 16384u;
            #pragma unroll
            for (int u = 0; u < 4; u++) {
                uint32_t h0, h1, l0, l1;
                cvt_pair(xv[(c + 1) & 1][u].x, xv[(c + 1) & 1][u].y, h0, l0);
                cvt_pair(xv[(c + 1) & 1][u].z, xv[(c + 1) & 1][u].w, h1, l1);
                STS64U(hb + stsH[u], h0, h1);
                STS64U(hb + 8192u + stsH[u], l0, l1);
            }
            BAR_HALF(h + 1);        // only this half convoys
        }
    }

    __syncthreads();    // both halves done; stage area reusable for partials

    // ---- k-half partials -> two [128][18] buffers ----
    {
        const uint32_t lb = sb + (uint32_t)kh * 9216u;
        const int rA = h * 64 + tgh * 16 + (l >> 2);
        const int rB = rA + 8;
        const int cb = 2 * (l & 3);
        STS64F(lb + (uint32_t)(rA * 18 + cb) * 4u,     d0[0], d0[1]);
        STS64F(lb + (uint32_t)(rB * 18 + cb) * 4u,     d0[2], d0[3]);
        STS64F(lb + (uint32_t)(rA * 18 + 8 + cb) * 4u, d1[0], d1[1]);
        STS64F(lb + (uint32_t)(rB * 18 + 8 + cb) * 4u, d1[2], d1[3]);
    }
    __syncthreads();

    // ---- epilogue: one token per thread (threads 0..127) ----
    if (tid < BT) {
        const int gtok = tok0 + tid;
        const float4* nz = (const float4*)(noise + (size_t)gtok * NE);
        float4 n0 = nz[0], n1 = nz[1], n2 = nz[2], n3 = nz[3];
        const float4* bb4 = (const float4*)b;
        float4 q0 = bb4[0], q1 = bb4[1], q2 = bb4[2], q3 = bb4[3];

        float nn[16] = {n0.x, n0.y, n0.z, n0.w, n1.x, n1.y, n1.z, n1.w,
                        n2.x, n2.y, n2.z, n2.w, n3.x, n3.y, n3.z, n3.w};
        float bv[16] = {q0.x, q0.y, q0.z, q0.w, q1.x, q1.y, q1.z, q1.w,
                        q2.x, q2.y, q2.z, q2.w, q3.x, q3.y, q3.z, q3.w};

        float v[16];
        #pragma unroll
        for (int e = 0; e < 16; e++) {
            float l0, l1;
            LDS32F(l0, sb + (uint32_t)(tid * 18 + e) * 4u);
            LDS32F(l1, sb + 9216u + (uint32_t)(tid * 18 + e) * 4u);
            v[e] = (l0 + l1) + bv[e] + 0.1f * nn[e];
        }

        // top-2 (stable: earlier index wins ties, matching jax top_k)
        float v1 = -1e30f, v2 = -1e30f;
        int   i1 = -1,     i2 = -1;
        #pragma unroll
        for (int e = 0; e < 16; e++) {
            float val = v[e];
            if (val > v1)      { v2 = v1; i2 = i1; v1 = val; i1 = e; }
            else if (val > v2) { v2 = val; i2 = e; }
        }

        float ew  = expf(v2 - v1);
        float inv = 1.0f / (1.0f + ew);
        float w1  = inv;
        float w2  = ew * inv;

        float o[16];
        #pragma unroll
        for (int e = 0; e < 16; e++)
            o[e] = (e == i1) ? w1 : ((e == i2) ? w2 : 0.0f);

        float4* op = (float4*)(out + (size_t)gtok * NE);
        op[0] = make_float4(o[0],  o[1],  o[2],  o[3]);
        op[1] = make_float4(o[4],  o[5],  o[6],  o[7]);
        op[2] = make_float4(o[8],  o[9],  o[10], o[11]);
        op[3] = make_float4(o[12], o[13], o[14], o[15]);
    }
}

extern "C" void kernel_launch(void* const* d_in, const int* in_sizes, int n_in,
                              void* d_out, int out_size)
{
    const float* x     = (const float*)d_in[0];
    const float* noise = (const float*)d_in[1];
    const float* W     = (const float*)d_in[2];
    const float* b     = (const float*)d_in[3];
    float* out = (float*)d_out;

    cudaFuncSetAttribute(gating_moe_kernel,
                         cudaFuncAttributeMaxDynamicSharedMemorySize, SMEM_BYTES);
    gating_moe_kernel<<<TOK / BT, NTHR, SMEM_BYTES>>>(x, noise, W, b, out);
}

// round 17
// speedup vs baseline: 1.2529x; 1.2529x over previous
#include <cuda_runtime.h>
#include <cstdint>

#define TOK    16384
#define DIM    2048
#define NE     16
#define BT     64          // tokens per CTA
#define NTHR   256
#define NCHUNK 16          // K chunks of 64 within this CTA's 1024-dim half

// smem: stages [0, 32768): stage s at s*16384 (hi 8K | lo 8K); W half-blob [32768, 98304)
#define WBo 32768u
#define SMEM_BYTES 98304   // 96 KB -> 2 CTAs/SM

__device__ float g_part[2][TOK * NE];   // per-k-half partial logits (fully rewritten each call)

__device__ __forceinline__ uint32_t smem_u32(const void* p) {
    uint32_t a;
    asm("{ .reg .u64 t; cvta.to.shared.u64 t, %1; cvt.u32.u64 %0, t; }" : "=r"(a) : "l"(p));
    return a;
}

#define STS32U(addr, v) asm volatile("st.shared.b32 [%0], %1;" :: "r"(addr), "r"(v) : "memory")
#define STS64U(addr, a, b) \
    asm volatile("st.shared.v2.b32 [%0], {%1, %2};" :: "r"(addr), "r"(a), "r"(b) : "memory")
#define STS64F(addr, a, b) \
    asm volatile("st.shared.v2.f32 [%0], {%1, %2};" :: "r"(addr), "f"(a), "f"(b) : "memory")
#define LDS128F(v0, v1, v2, v3, addr) \
    asm volatile("ld.shared.v4.f32 {%0,%1,%2,%3}, [%4];" \
        : "=f"(v0), "=f"(v1), "=f"(v2), "=f"(v3) : "r"(addr))
#define LDS32U(v, addr) asm volatile("ld.shared.b32 %0, [%1];" : "=r"(v) : "r"(addr))

#define LDMX4(r0, r1, r2, r3, addr) \
    asm volatile("ldmatrix.sync.aligned.m8n8.x4.shared.b16 {%0,%1,%2,%3}, [%4];" \
        : "=r"(r0), "=r"(r1), "=r"(r2), "=r"(r3) : "r"(addr))

#define MMA_BF16(d, a0, a1, a2, a3, b0, b1)                                \
    asm volatile("mma.sync.aligned.m16n8k16.row.col.f32.bf16.bf16.f32 "    \
        "{%0,%1,%2,%3},{%4,%5,%6,%7},{%8,%9},{%0,%1,%2,%3};"               \
        : "+f"(d[0]), "+f"(d[1]), "+f"(d[2]), "+f"(d[3])                   \
        : "r"(a0), "r"(a1), "r"(a2), "r"(a3), "r"(b0), "r"(b1))

// f32 pair -> packed bf16x2 hi (truncation; low half = f0) + bf16x2 lo (rounded residual)
__device__ __forceinline__ void cvt_pair(float f0, float f1, uint32_t& hi, uint32_t& lo) {
    uint32_t u0 = __float_as_uint(f0) & 0xffff0000u;
    uint32_t u1 = __float_as_uint(f1) & 0xffff0000u;
    asm("prmt.b32 %0, %1, %2, 0x7632;" : "=r"(hi) : "r"(u0), "r"(u1));
    float l0 = f0 - __uint_as_float(u0);
    float l1 = f1 - __uint_as_float(u1);
    asm("cvt.rn.bf16x2.f32 %0, %1, %2;" : "=r"(lo) : "f"(l1), "f"(l0));
}

__global__ void __launch_bounds__(NTHR, 2)
gating_gemm_kernel(const float* __restrict__ x, const float* __restrict__ W)
{
    extern __shared__ float sm[];
    const uint32_t sb = smem_u32(sm);
    const int tid  = threadIdx.x;
    const int l    = tid & 31;
    const int w    = tid >> 5;
    const int tg   = w & 3;          // token group (16 tokens)
    const int kgs  = w >> 2;         // kg-pair selector within a chunk
    const int tb   = blockIdx.x >> 1;
    const int kh   = blockIdx.x & 1; // k-half: dims [kh*1024, +1024)
    const int tok0 = tb * BT;
    const int koff = kh * 1024;

    // ---- one-time W half-blob: [kgg 0..63] x 1024 B (et0 512 | et1 512);
    //      per et: hi k0-7 (128) | hi k8-15 | lo k0-7 | lo k8-15; row=expert, u32=k-pair
    #pragma unroll
    for (int k = 0; k < 32; k++) {
        int idx = tid + NTHR * k;        // 8192 k-pairs in this half
        int e   = idx >> 9;              // expert 0..15
        int pd  = idx & 511;             // k-pair within half
        float2 wv = *(const float2*)(W + (size_t)e * DIM + koff + 2 * pd);
        uint32_t hh, lo;
        cvt_pair(wv.x, wv.y, hh, lo);
        int kgg = pd >> 3;
        int p   = pd & 7;
        uint32_t base = sb + WBo + (uint32_t)(kgg * 1024 + (e >> 3) * 512);
        uint32_t off  = (uint32_t)((p >> 2) * 128 + (e & 7) * 16 + (p & 3) * 4);
        STS32U(base + off, hh);
        STS32U(base + off + 256u, lo);
    }

    // ---- coalesced producer: 64 tok x 64 dims per chunk = 1024 f4, 4/thread ----
    const int r0q = tid >> 4;            // rows r0q + 16u
    const int sl  = tid & 15;
    const float* xg = x + (size_t)(tok0 + r0q) * DIM + koff + sl * 4;
    uint32_t stsH[4];
    #pragma unroll
    for (int u = 0; u < 4; u++) {
        uint32_t o = (uint32_t)(((r0q + 16 * u) * 128) + sl * 8);
        stsH[u] = o ^ ((o >> 3) & 0x70u);
    }

    // ---- consumer geometry (R15-identical) ----
    const uint32_t rowterm = (uint32_t)((tg * 16 + (l & 15)) * 128 + ((l >> 4) << 4));
    const uint32_t lanB    = (uint32_t)((l >> 2) * 16 + (l & 3) * 4);

    float d0[4] = {0.f, 0.f, 0.f, 0.f};   // experts 0-7
    float d1[4] = {0.f, 0.f, 0.f, 0.f};   // experts 8-15
    float4 xv[4];

    // produce chunk 0 into stage 0
    #pragma unroll
    for (int u = 0; u < 4; u++) xv[u] = *(const float4*)(xg + u * 16 * DIM);
    #pragma unroll
    for (int u = 0; u < 4; u++) {
        uint32_t h0, h1, l0, l1;
        cvt_pair(xv[u].x, xv[u].y, h0, l0);
        cvt_pair(xv[u].z, xv[u].w, h1, l1);
        STS64U(sb + stsH[u], h0, h1);
        STS64U(sb + 8192u + stsH[u], l0, l1);
    }
    __syncthreads();

    for (int c = 0; c < NCHUNK; c++) {
        if (c + 1 < NCHUNK) {
            #pragma unroll
            for (int u = 0; u < 4; u++)
                xv[u] = *(const float4*)(xg + (c + 1) * 64 + u * 16 * DIM);
        }

        // ---- consume stage c&1: kg = kgs*2 + {0,1} ----
        const uint32_t ab = sb + (uint32_t)(c & 1) * 16384u;
        #pragma unroll
        for (int kgl = 0; kgl < 2; kgl++) {
            const int kg = kgs * 2 + kgl;
            uint32_t lg = rowterm + (uint32_t)(kg * 32);
            uint32_t sw = lg ^ ((lg >> 3) & 0x70u);
            uint32_t ah0, ah1, ah2, ah3, al0, al1, al2, al3;
            LDMX4(ah0, ah1, ah2, ah3, ab + sw);
            LDMX4(al0, al1, al2, al3, ab + 8192u + sw);

            const uint32_t kb = sb + WBo + (uint32_t)((c * 4 + kg) * 1024) + lanB;
            uint32_t b0h0, b0h1, b0l0, b0l1, b1h0, b1h1, b1l0, b1l1;
            LDS32U(b0h0, kb);           LDS32U(b0h1, kb + 128u);
            LDS32U(b0l0, kb + 256u);    LDS32U(b0l1, kb + 384u);
            LDS32U(b1h0, kb + 512u);    LDS32U(b1h1, kb + 640u);
            LDS32U(b1l0, kb + 768u);    LDS32U(b1l1, kb + 896u);

            MMA_BF16(d0, ah0, ah1, ah2, ah3, b0h0, b0h1);
            MMA_BF16(d0, ah0, ah1, ah2, ah3, b0l0, b0l1);
            MMA_BF16(d0, al0, al1, al2, al3, b0h0, b0h1);
            MMA_BF16(d1, ah0, ah1, ah2, ah3, b1h0, b1h1);
            MMA_BF16(d1, ah0, ah1, ah2, ah3, b1l0, b1l1);
            MMA_BF16(d1, al0, al1, al2, al3, b1h0, b1h1);
        }

        // ---- produce chunk c+1 into the other stage ----
        if (c + 1 < NCHUNK) {
            const uint32_t hb = sb + (uint32_t)((c + 1) & 1) * 16384u;
            #pragma unroll
            for (int u = 0; u < 4; u++) {
                uint32_t h0, h1, l0, l1;
                cvt_pair(xv[u].x, xv[u].y, h0, l0);
                cvt_pair(xv[u].z, xv[u].w, h1, l1);
                STS64U(hb + stsH[u], h0, h1);
                STS64U(hb + 8192u + stsH[u], l0, l1);
            }
        }
        __syncthreads();
    }

    // ---- kg-pair partials -> two [64][20] buffers (reuse stage area) ----
    {
        const uint32_t lb = sb + (uint32_t)kgs * 5120u;
        const int rA = tg * 16 + (l >> 2);
        const int rB = rA + 8;
        const int cb = 2 * (l & 3);
        STS64F(lb + (uint32_t)(rA * 20 + cb) * 4u,     d0[0], d0[1]);
        STS64F(lb + (uint32_t)(rB * 20 + cb) * 4u,     d0[2], d0[3]);
        STS64F(lb + (uint32_t)(rA * 20 + 8 + cb) * 4u, d1[0], d1[1]);
        STS64F(lb + (uint32_t)(rB * 20 + 8 + cb) * 4u, d1[2], d1[3]);
    }
    __syncthreads();

    // ---- store this CTA's 64x16 partial logits to global ----
    {
        const int t = tid >> 2;          // token 0..63
        const int q = tid & 3;           // expert quad
        const uint32_t a0 = sb + (uint32_t)(t * 20 + 4 * q) * 4u;
        float p0, p1, p2, p3, q0, q1, q2, q3;
        LDS128F(p0, p1, p2, p3, a0);
        LDS128F(q0, q1, q2, q3, a0 + 5120u);
        float4 v = make_float4(p0 + q0, p1 + q1, p2 + q2, p3 + q3);
        *(float4*)(&g_part[kh][(size_t)(tok0 + t) * NE + 4 * q]) = v;
    }
}

__global__ void __launch_bounds__(128, 8)
gating_epilogue_kernel(const float* __restrict__ noise,
                       const float* __restrict__ b,
                       float* __restrict__ out)
{
    const int tk = blockIdx.x * 128 + threadIdx.x;

    const float4* p0 = (const float4*)(&g_part[0][(size_t)tk * NE]);
    const float4* p1 = (const float4*)(&g_part[1][(size_t)tk * NE]);
    const float4* nz = (const float4*)(noise + (size_t)tk * NE);
    const float4* bb4 = (const float4*)b;

    float v[16];
    #pragma unroll
    for (int j = 0; j < 4; j++) {
        float4 a = p0[j], c = p1[j], n = nz[j], q = bb4[j];
        v[4 * j + 0] = a.x + c.x + q.x + 0.1f * n.x;
        v[4 * j + 1] = a.y + c.y + q.y + 0.1f * n.y;
        v[4 * j + 2] = a.z + c.z + q.z + 0.1f * n.z;
        v[4 * j + 3] = a.w + c.w + q.w + 0.1f * n.w;
    }

    // top-2 (stable: earlier index wins ties, matching jax top_k)
    float v1 = -1e30f, v2 = -1e30f;
    int   i1 = -1,     i2 = -1;
    #pragma unroll
    for (int e = 0; e < 16; e++) {
        float val = v[e];
        if (val > v1)      { v2 = v1; i2 = i1; v1 = val; i1 = e; }
        else if (val > v2) { v2 = val; i2 = e; }
    }

    float ew  = expf(v2 - v1);
    float inv = 1.0f / (1.0f + ew);
    float w1  = inv;
    float w2  = ew * inv;

    float o[16];
    #pragma unroll
    for (int e = 0; e < 16; e++)
        o[e] = (e == i1) ? w1 : ((e == i2) ? w2 : 0.0f);

    float4* op = (float4*)(out + (size_t)tk * NE);
    op[0] = make_float4(o[0],  o[1],  o[2],  o[3]);
    op[1] = make_float4(o[4],  o[5],  o[6],  o[7]);
    op[2] = make_float4(o[8],  o[9],  o[10], o[11]);
    op[3] = make_float4(o[12], o[13], o[14], o[15]);
}

extern "C" void kernel_launch(void* const* d_in, const int* in_sizes, int n_in,
                              void* d_out, int out_size)
{
    const float* x     = (const float*)d_in[0];
    const float* noise = (const float*)d_in[1];
    const float* W     = (const float*)d_in[2];
    const float* b     = (const float*)d_in[3];
    float* out = (float*)d_out;

    cudaFuncSetAttribute(gating_gemm_kernel,
                         cudaFuncAttributeMaxDynamicSharedMemorySize, SMEM_BYTES);
    gating_gemm_kernel<<<(TOK / BT) * 2, NTHR, SMEM_BYTES>>>(x, W);
    gating_epilogue_kernel<<<TOK / 128, 128>>>(noise, b, out);
}